// round 16
// baseline (speedup 1.0000x reference)
#include <cuda_runtime.h>
#include <cuda_fp16.h>
#include <math.h>

#define B_   4
#define L_   2048
#define D_   512
#define S_   256
#define NL_  6
#define H_   8
#define DH_  64
#define WIN_ 256

// ---------------- scratch (device globals; no allocation) ----------------
__device__ float g_X[B_*L_*D_];         // out-proj fp32 scratch
__device__ float g_STATE[B_*D_];
__device__ float g_PART[128][B_][S_];
__device__ int   g_CNT[NL_*B_];

__device__ __half g_Uh[B_*L_*S_];       // mamba u (fp16)
__device__ __half g_Xh[B_*L_*D_];       // conv output (layer 0 only)
__device__ __half g_SEQh[B_*L_*D_];     // ln output fp16 shadow
__device__ __half g_QKVh[B_*L_*3*D_];   // qkv fp16
__device__ __half g_ATTh[B_*L_*D_];     // attention context fp16
__device__ __half g_WxH[NL_*D_*S_];     // [D][S]
__device__ __half g_WqkvH[3*D_*D_];     // [3D][D]
__device__ __half g_WoH[D_*D_];         // [D][D]

// ---------------- helpers ----------------
__device__ __forceinline__ void gds() {
    asm volatile("griddepcontrol.wait;" ::: "memory");
}
__device__ __forceinline__ void ldsm4(unsigned& r0, unsigned& r1, unsigned& r2, unsigned& r3, unsigned addr) {
    asm volatile("ldmatrix.sync.aligned.m8n8.x4.shared.b16 {%0,%1,%2,%3},[%4];"
                 : "=r"(r0), "=r"(r1), "=r"(r2), "=r"(r3) : "r"(addr));
}
__device__ __forceinline__ void ldsm4t(unsigned& r0, unsigned& r1, unsigned& r2, unsigned& r3, unsigned addr) {
    asm volatile("ldmatrix.sync.aligned.m8n8.x4.trans.shared.b16 {%0,%1,%2,%3},[%4];"
                 : "=r"(r0), "=r"(r1), "=r"(r2), "=r"(r3) : "r"(addr));
}
__device__ __forceinline__ void mma16816(float* c, const unsigned* a, const unsigned* b) {
    asm volatile("mma.sync.aligned.m16n8k16.row.col.f32.f16.f16.f32 "
                 "{%0,%1,%2,%3},{%4,%5,%6,%7},{%8,%9},{%0,%1,%2,%3};"
                 : "+f"(c[0]), "+f"(c[1]), "+f"(c[2]), "+f"(c[3])
                 : "r"(a[0]), "r"(a[1]), "r"(a[2]), "r"(a[3]), "r"(b[0]), "r"(b[1]));
}
__device__ __forceinline__ void cpa16(unsigned d, const void* s) {
    asm volatile("cp.async.cg.shared.global [%0],[%1],16;" :: "r"(d), "l"(s));
}
__device__ __forceinline__ void cpa_commit() {
    asm volatile("cp.async.commit_group;");
}
template <int N>
__device__ __forceinline__ void cpa_wait() {
    asm volatile("cp.async.wait_group %0;" :: "n"(N));
}

// ---------------- merged weight conversion + counter reset ----------------
#define NWX (NL_*D_*S_)
#define NWQ (3*D_*D_)
#define NWO (D_*D_)
__global__ void cvt_weights_all(const float* __restrict__ Wx,
                                const float* __restrict__ Wqkv,
                                const float* __restrict__ Wo) {
    gds();
    int t = blockIdx.x * 256 + threadIdx.x;
    if (t < NL_ * B_) g_CNT[t] = 0;
    if (t < NWX) {
        g_WxH[t] = __float2half_rn(Wx[t]);
    } else if (t < NWX + NWQ) {
        int u = t - NWX;
        g_WqkvH[u] = __float2half_rn(Wqkv[u]);
    } else if (t < NWX + NWQ + NWO) {
        int u = t - NWX - NWQ;
        g_WoH[u] = __float2half_rn(Wo[u]);
    }
}

// ---------------- conv (k=3, causal) + SiLU -> fp16 (layer 0 only) ------
__global__ void conv_silu_f32(const float* __restrict__ seq,
                              const float* __restrict__ cw) {
    gds();
    int row = blockIdx.x;
    int l = row & (L_ - 1);
    int t = threadIdx.x;
    float4 z = make_float4(0.f, 0.f, 0.f, 0.f);
    float4 a0 = (l >= 2) ? ((const float4*)(seq + (size_t)(row - 2) * D_))[t] : z;
    float4 a1 = (l >= 1) ? ((const float4*)(seq + (size_t)(row - 1) * D_))[t] : z;
    float4 a2 = ((const float4*)(seq + (size_t)row * D_))[t];
    float4 w0 = ((const float4*)(cw        ))[t];
    float4 w1 = ((const float4*)(cw +   D_ ))[t];
    float4 w2 = ((const float4*)(cw + 2*D_ ))[t];
    float x0 = w0.x*a0.x + w1.x*a1.x + w2.x*a2.x;
    float x1 = w0.y*a0.y + w1.y*a1.y + w2.y*a2.y;
    float x2 = w0.z*a0.z + w1.z*a1.z + w2.z*a2.z;
    float x3 = w0.w*a0.w + w1.w*a1.w + w2.w*a2.w;
    x0 = x0 / (1.f + __expf(-x0));
    x1 = x1 / (1.f + __expf(-x1));
    x2 = x2 / (1.f + __expf(-x2));
    x3 = x3 / (1.f + __expf(-x3));
    size_t o = (size_t)row * D_ + t * 4;
    *(__half2*)&g_Xh[o]     = __floats2half2_rn(x0, x1);
    *(__half2*)&g_Xh[o + 2] = __floats2half2_rn(x2, x3);
}

// ---------------- fp16 cp.async GEMM, 128x128 tile, K-chunk 64 ----------
#define GA_STR 72
#define GA_SZ  (128 * GA_STR)
#define GB1_SZ (128 * GA_STR)
#define GB0_SZ (64 * 136)
extern __shared__ __half smg[];

template <int TB>
__global__ void __launch_bounds__(256) mma_gemm4(const __half* __restrict__ A,
                                                 const __half* __restrict__ Bm,
                                                 const float* __restrict__ bias,
                                                 float* __restrict__ Cf,
                                                 __half* __restrict__ Ch,
                                                 int M, int N, int K) {
    gds();
    constexpr int BSZ = TB ? GB1_SZ : GB0_SZ;
    int bm = blockIdx.y * 128, bn = blockIdx.x * 128;
    int tid = threadIdx.x;
    int lane = tid & 31, wid = tid >> 5;
    int wm = (wid & 3) * 32;
    int wn = (wid >> 2) * 64;

    float acc[2][8][4];
#pragma unroll
    for (int i = 0; i < 2; i++)
#pragma unroll
        for (int j = 0; j < 8; j++)
#pragma unroll
            for (int k = 0; k < 4; k++) acc[i][j][k] = 0.f;

    unsigned sbase = (unsigned)__cvta_generic_to_shared(smg);

    int nk = K >> 6;
    auto issue = [&](int kt) {
        unsigned sa = sbase + (unsigned)((kt & 1) * GA_SZ) * 2u;
        unsigned sb = sbase + (unsigned)(2 * GA_SZ + (kt & 1) * BSZ) * 2u;
        int k0 = kt << 6;
#pragma unroll
        for (int j = 0; j < 4; j++) {
            int ch = tid + 256 * j;
            int r = ch >> 3, c8 = (ch & 7) * 8;
            cpa16(sa + (unsigned)(r * GA_STR + c8) * 2u,
                  A + (size_t)(bm + r) * K + k0 + c8);
        }
        if (TB == 1) {
#pragma unroll
            for (int j = 0; j < 4; j++) {
                int ch = tid + 256 * j;
                int r = ch >> 3, c8 = (ch & 7) * 8;
                cpa16(sb + (unsigned)(r * GA_STR + c8) * 2u,
                      Bm + (size_t)(bn + r) * K + k0 + c8);
            }
        } else {
#pragma unroll
            for (int j = 0; j < 4; j++) {
                int ch = tid + 256 * j;
                int r = ch >> 4, c8 = (ch & 15) * 8;
                cpa16(sb + (unsigned)(r * 136 + c8) * 2u,
                      Bm + (size_t)(k0 + r) * N + bn + c8);
            }
        }
        cpa_commit();
    };

    issue(0);
    for (int kt = 0; kt < nk; kt++) {
        if (kt + 1 < nk) { issue(kt + 1); cpa_wait<1>(); }
        else             { cpa_wait<0>(); }
        __syncthreads();

        unsigned sa = sbase + (unsigned)((kt & 1) * GA_SZ) * 2u;
        unsigned sb = sbase + (unsigned)(2 * GA_SZ + (kt & 1) * BSZ) * 2u;
#pragma unroll
        for (int ks = 0; ks < 4; ks++) {
            unsigned af[2][4], bf[8][2];
#pragma unroll
            for (int mi = 0; mi < 2; mi++) {
                int row = wm + mi * 16 + (lane & 15);
                unsigned off = (unsigned)(row * GA_STR + ks * 16 + (lane >> 4) * 8) * 2u;
                ldsm4(af[mi][0], af[mi][1], af[mi][2], af[mi][3], sa + off);
            }
            if (TB == 1) {
#pragma unroll
                for (int nh = 0; nh < 4; nh++) {
                    int row = wn + nh * 16 + (lane & 15);
                    unsigned off = (unsigned)(row * GA_STR + ks * 16 + (lane >> 4) * 8) * 2u;
                    unsigned r0, r1, r2, r3;
                    ldsm4(r0, r1, r2, r3, sb + off);
                    bf[nh*2+0][0] = r0; bf[nh*2+0][1] = r2;
                    bf[nh*2+1][0] = r1; bf[nh*2+1][1] = r3;
                }
            } else {
#pragma unroll
                for (int nh = 0; nh < 4; nh++) {
                    int row = ks * 16 + (lane & 15);
                    unsigned off = (unsigned)(row * 136 + wn + nh * 16 + (lane >> 4) * 8) * 2u;
                    unsigned r0, r1, r2, r3;
                    ldsm4t(r0, r1, r2, r3, sb + off);
                    bf[nh*2+0][0] = r0; bf[nh*2+0][1] = r1;
                    bf[nh*2+1][0] = r2; bf[nh*2+1][1] = r3;
                }
            }
#pragma unroll
            for (int mi = 0; mi < 2; mi++)
#pragma unroll
                for (int ni = 0; ni < 8; ni++)
                    mma16816(acc[mi][ni], af[mi], bf[ni]);
        }
        __syncthreads();
    }

#pragma unroll
    for (int mi = 0; mi < 2; mi++)
#pragma unroll
        for (int ni = 0; ni < 8; ni++) {
            int r = bm + wm + mi * 16 + (lane >> 2);
            int c = bn + wn + ni * 8 + (lane & 3) * 2;
            float b0 = bias ? bias[c] : 0.f;
            float b1 = bias ? bias[c + 1] : 0.f;
            float v00 = acc[mi][ni][0] + b0, v01 = acc[mi][ni][1] + b1;
            float v10 = acc[mi][ni][2] + b0, v11 = acc[mi][ni][3] + b1;
            if (Ch) {
                *(__half2*)&Ch[(size_t)r * N + c]       = __floats2half2_rn(v00, v01);
                *(__half2*)&Ch[(size_t)(r + 8) * N + c] = __floats2half2_rn(v10, v11);
            } else {
                Cf[(size_t)r * N + c]           = v00;
                Cf[(size_t)r * N + c + 1]       = v01;
                Cf[(size_t)(r + 8) * N + c]     = v10;
                Cf[(size_t)(r + 8) * N + c + 1] = v11;
            }
        }
}

// ---------------- conv-fused mamba GEMM (layers 1-5) ----------------
// A = conv(SEQh)+SiLU computed on the fly; B = WxH [K][N]; C = Uh fp16.
__global__ void __launch_bounds__(256) mma_gemm_conv(const __half* __restrict__ SEQ,
                                                     const float* __restrict__ cw,
                                                     const __half* __restrict__ Bm,
                                                     __half* __restrict__ Ch,
                                                     int M, int N, int K) {
    gds();
    int bm = blockIdx.y * 128, bn = blockIdx.x * 128;
    int tid = threadIdx.x;
    int lane = tid & 31, wid = tid >> 5;
    int wm = (wid & 3) * 32;
    int wn = (wid >> 2) * 64;

    float acc[2][8][4];
#pragma unroll
    for (int i = 0; i < 2; i++)
#pragma unroll
        for (int j = 0; j < 8; j++)
#pragma unroll
            for (int k = 0; k < 4; k++) acc[i][j][k] = 0.f;

    unsigned sbase = (unsigned)__cvta_generic_to_shared(smg);
    int nk = K >> 6;

    uint4 v0[4], v1[4], v2[4];
    auto loadA = [&](int kt) {
        int k0 = kt << 6;
#pragma unroll
        for (int j = 0; j < 4; j++) {
            int ch = tid + 256 * j;
            int r = ch >> 3, c8 = (ch & 7) * 8;
            int row = bm + r;
            int l = row & (L_ - 1);
            size_t base = (size_t)row * K + k0 + c8;
            uint4 z4 = make_uint4(0u, 0u, 0u, 0u);
            v2[j] = *(const uint4*)(SEQ + base);
            v1[j] = (l >= 1) ? *(const uint4*)(SEQ + base - K) : z4;
            v0[j] = (l >= 2) ? *(const uint4*)(SEQ + base - 2 * K) : z4;
        }
    };
    auto storeA = [&](int kt) {
        int k0 = kt << 6;
#pragma unroll
        for (int j = 0; j < 4; j++) {
            int ch = tid + 256 * j;
            int r = ch >> 3, c8 = (ch & 7) * 8;
            const float* cp = cw + k0 + c8;
            float4 wa0 = *(const float4*)(cp);
            float4 wb0 = *(const float4*)(cp + 4);
            float4 wa1 = *(const float4*)(cp + D_);
            float4 wb1 = *(const float4*)(cp + D_ + 4);
            float4 wa2 = *(const float4*)(cp + 2 * D_);
            float4 wb2 = *(const float4*)(cp + 2 * D_ + 4);
            float w0[8] = {wa0.x, wa0.y, wa0.z, wa0.w, wb0.x, wb0.y, wb0.z, wb0.w};
            float w1[8] = {wa1.x, wa1.y, wa1.z, wa1.w, wb1.x, wb1.y, wb1.z, wb1.w};
            float w2[8] = {wa2.x, wa2.y, wa2.z, wa2.w, wb2.x, wb2.y, wb2.z, wb2.w};
            const __half2* h0 = (const __half2*)&v0[j];
            const __half2* h1 = (const __half2*)&v1[j];
            const __half2* h2 = (const __half2*)&v2[j];
            uint4 outv;
            __half2* ov = (__half2*)&outv;
#pragma unroll
            for (int e = 0; e < 4; e++) {
                float2 f0 = __half22float2(h0[e]);
                float2 f1 = __half22float2(h1[e]);
                float2 f2 = __half22float2(h2[e]);
                float xa = w0[2*e]   * f0.x + w1[2*e]   * f1.x + w2[2*e]   * f2.x;
                float xb = w0[2*e+1] * f0.y + w1[2*e+1] * f1.y + w2[2*e+1] * f2.y;
                xa = xa / (1.f + __expf(-xa));
                xb = xb / (1.f + __expf(-xb));
                ov[e] = __floats2half2_rn(xa, xb);
            }
            *(uint4*)((char*)smg + (size_t)((kt & 1) * GA_SZ + r * GA_STR + c8) * 2) = outv;
        }
    };
    auto issueB = [&](int kt) {
        unsigned sb = sbase + (unsigned)(2 * GA_SZ + (kt & 1) * GB0_SZ) * 2u;
        int k0 = kt << 6;
#pragma unroll
        for (int j = 0; j < 4; j++) {
            int ch = tid + 256 * j;
            int r = ch >> 4, c8 = (ch & 15) * 8;
            cpa16(sb + (unsigned)(r * 136 + c8) * 2u,
                  Bm + (size_t)(k0 + r) * N + bn + c8);
        }
        cpa_commit();
    };

    loadA(0);
    issueB(0);
    for (int kt = 0; kt < nk; kt++) {
        storeA(kt);
        if (kt + 1 < nk) { issueB(kt + 1); loadA(kt + 1); cpa_wait<1>(); }
        else             { cpa_wait<0>(); }
        __syncthreads();

        unsigned sa = sbase + (unsigned)((kt & 1) * GA_SZ) * 2u;
        unsigned sb = sbase + (unsigned)(2 * GA_SZ + (kt & 1) * GB0_SZ) * 2u;
#pragma unroll
        for (int ks = 0; ks < 4; ks++) {
            unsigned af[2][4], bf[8][2];
#pragma unroll
            for (int mi = 0; mi < 2; mi++) {
                int row = wm + mi * 16 + (lane & 15);
                unsigned off = (unsigned)(row * GA_STR + ks * 16 + (lane >> 4) * 8) * 2u;
                ldsm4(af[mi][0], af[mi][1], af[mi][2], af[mi][3], sa + off);
            }
#pragma unroll
            for (int nh = 0; nh < 4; nh++) {
                int row = ks * 16 + (lane & 15);
                unsigned off = (unsigned)(row * 136 + wn + nh * 16 + (lane >> 4) * 8) * 2u;
                unsigned r0, r1, r2, r3;
                ldsm4t(r0, r1, r2, r3, sb + off);
                bf[nh*2+0][0] = r0; bf[nh*2+0][1] = r1;
                bf[nh*2+1][0] = r2; bf[nh*2+1][1] = r3;
            }
#pragma unroll
            for (int mi = 0; mi < 2; mi++)
#pragma unroll
                for (int ni = 0; ni < 8; ni++)
                    mma16816(acc[mi][ni], af[mi], bf[ni]);
        }
        __syncthreads();
    }

#pragma unroll
    for (int mi = 0; mi < 2; mi++)
#pragma unroll
        for (int ni = 0; ni < 8; ni++) {
            int r = bm + wm + mi * 16 + (lane >> 2);
            int c = bn + wn + ni * 8 + (lane & 3) * 2;
            *(__half2*)&Ch[(size_t)r * N + c] =
                __floats2half2_rn(acc[mi][ni][0], acc[mi][ni][1]);
            *(__half2*)&Ch[(size_t)(r + 8) * N + c] =
                __floats2half2_rn(acc[mi][ni][2], acc[mi][ni][3]);
        }
}

// ---------------- merged ssm: Horner parts + last-block combine ----------
__global__ void __launch_bounds__(256) ht_merged(const float* __restrict__ Aparam,
                                                 const float* __restrict__ Wh,
                                                 const float* __restrict__ Wout,
                                                 int layer, int first) {
    gds();
    __shared__ int isLast;
    __shared__ float sh_ht[S_];
    int b = blockIdx.x, c = blockIdx.y;   // 128 chunks of 16
    int s = threadIdx.x;                  // 256
    float a = 1.f / (1.f + expf(-Aparam[s]));
    {
        float wt = powf(a, (float)(16 * (127 - c)));
        float wmax = wt;
        for (int off = 16; off; off >>= 1)
            wmax = fmaxf(wmax, __shfl_xor_sync(0xffffffffu, wmax, off));
        float p = 0.f;
        if (wmax >= 1e-28f) {
            const __half* base = g_Uh + ((size_t)(b * L_) + c * 16) * S_ + s;
#pragma unroll
            for (int j = 0; j < 16; j++) p = p * a + __half2float(base[(size_t)j * S_]);
            p *= wt;
        }
        g_PART[c][b][s] = p;
    }
    __threadfence();
    __syncthreads();
    if (threadIdx.x == 0)
        isLast = (atomicAdd(&g_CNT[layer * B_ + b], 1) == 127) ? 1 : 0;
    __syncthreads();
    if (!isLast) return;
    __threadfence();

    // combine (one block per b)
    float h0 = 0.f;
    if (!first) {
#pragma unroll 8
        for (int d = 0; d < D_; d++)
            h0 += g_STATE[b * D_ + d] * Wh[(size_t)d * S_ + s];
    }
    float ps = 0.f;
#pragma unroll
    for (int c2 = 0; c2 < 128; c2++) ps += g_PART[c2][b][s];
    sh_ht[s] = powf(a, (float)L_) * h0 + ps;
    __syncthreads();
#pragma unroll
    for (int d0 = 0; d0 < 2; d0++) {
        int d = s + d0 * 256;
        float acc = 0.f;
#pragma unroll 8
        for (int ss = 0; ss < S_; ss++) acc += sh_ht[ss] * Wout[(size_t)ss * D_ + d];
        g_STATE[b * D_ + d] = acc;
    }
}

// ---------------- residual + LayerNorm (optional fp16 shadow) ------------
__global__ void ln_kernel(const float* __restrict__ seq, const float* __restrict__ add,
                          const float* __restrict__ gamma, const float* __restrict__ beta,
                          float* __restrict__ out, int bcast, int writeh) {
    gds();
    __shared__ float red[4];
    __shared__ float stat;
    int row = blockIdx.x;
    int b = row >> 11;
    int t = threadIdx.x;   // 128
    float4 x = ((const float4*)(seq + (size_t)row * D_))[t];
    const float* ap = bcast ? (g_STATE + (size_t)b * D_) : (add + (size_t)row * D_);
    float4 a4 = ((const float4*)ap)[t];
    x.x += a4.x; x.y += a4.y; x.z += a4.z; x.w += a4.w;

    float sum = x.x + x.y + x.z + x.w;
    for (int off = 16; off; off >>= 1) sum += __shfl_xor_sync(0xffffffffu, sum, off);
    if ((t & 31) == 0) red[t >> 5] = sum;
    __syncthreads();
    if (t == 0) stat = (red[0] + red[1] + red[2] + red[3]) * (1.f / D_);
    __syncthreads();
    float mu = stat;
    float d0 = x.x - mu, d1 = x.y - mu, d2 = x.z - mu, d3 = x.w - mu;
    float sq = d0*d0 + d1*d1 + d2*d2 + d3*d3;
    for (int off = 16; off; off >>= 1) sq += __shfl_xor_sync(0xffffffffu, sq, off);
    if ((t & 31) == 0) red[t >> 5] = sq;
    __syncthreads();
    if (t == 0) stat = rsqrtf((red[0] + red[1] + red[2] + red[3]) * (1.f / D_) + 1e-5f);
    __syncthreads();
    float rs = stat;
    float4 g = ((const float4*)gamma)[t], be = ((const float4*)beta)[t];
    float4 y;
    y.x = d0 * rs * g.x + be.x;
    y.y = d1 * rs * g.y + be.y;
    y.z = d2 * rs * g.z + be.z;
    y.w = d3 * rs * g.w + be.w;
    ((float4*)(out + (size_t)row * D_))[t] = y;
    if (writeh) {
        size_t o = (size_t)row * D_ + t * 4;
        *(__half2*)&g_SEQh[o]     = __floats2half2_rn(y.x, y.y);
        *(__half2*)&g_SEQh[o + 2] = __floats2half2_rn(y.z, y.w);
    }
}

// ---------------- banded flash attention, fp16 MMA, cp.async K/V pipe ---
#define ATT_STR 72
#define ATT_T   (64 * ATT_STR)
extern __shared__ __half s_att[];

__global__ void __launch_bounds__(128) attn_mma_kernel() {
    gds();
    int b = blockIdx.z, h = blockIdx.y, q0 = blockIdx.x * 64;
    int tid = threadIdx.x, lane = tid & 31, w = tid >> 5;

    unsigned sQ = (unsigned)__cvta_generic_to_shared(s_att);

    int kstart = q0 - WIN_; if (kstart < 0) kstart = 0;
    int kend = q0 + 64 + WIN_; if (kend > L_) kend = L_;
    int nkt = (kend - kstart) >> 6;

    auto issue = [&](int t) {
        unsigned sk = sQ + (unsigned)(ATT_T * (1 + 2 * (t & 1))) * 2u;
        unsigned sv = sk + (unsigned)ATT_T * 2u;
        int k0 = kstart + t * 64;
#pragma unroll
        for (int j = 0; j < 4; j++) {
            int idx = tid + 128 * j;
            int r = idx >> 3, c = (idx & 7) * 8;
            size_t base = (size_t)(b * L_ + k0 + r) * (3 * D_) + h * DH_ + c;
            unsigned doff = (unsigned)(r * ATT_STR + c) * 2u;
            cpa16(sk + doff, g_QKVh + base + D_);
            cpa16(sv + doff, g_QKVh + base + 2 * D_);
        }
        cpa_commit();
    };

    issue(0);
#pragma unroll
    for (int j = 0; j < 4; j++) {
        int idx = tid + 128 * j;
        int r = idx >> 3, c = (idx & 7) * 8;
        *(uint4*)&s_att[r * ATT_STR + c] =
            *(const uint4*)(g_QKVh + (size_t)(b * L_ + q0 + r) * (3 * D_) + h * DH_ + c);
    }

    float m0 = -1e30f, m1 = -1e30f, l0s = 0.f, l1s = 0.f;
    float o[8][4];
#pragma unroll
    for (int j = 0; j < 8; j++)
#pragma unroll
        for (int r = 0; r < 4; r++) o[j][r] = 0.f;

    int qrow0 = 16 * w + (lane >> 2);

    for (int t = 0; t < nkt; t++) {
        if (t + 1 < nkt) { issue(t + 1); cpa_wait<1>(); }
        else             { cpa_wait<0>(); }
        __syncthreads();

        unsigned sK = sQ + (unsigned)(ATT_T * (1 + 2 * (t & 1))) * 2u;
        unsigned sV = sK + (unsigned)ATT_T * 2u;
        int k0 = kstart + t * 64;

        float sc[8][4];
#pragma unroll
        for (int j = 0; j < 8; j++)
#pragma unroll
            for (int r = 0; r < 4; r++) sc[j][r] = 0.f;

#pragma unroll
        for (int kk = 0; kk < 4; kk++) {
            unsigned aq[4];
            int qrow = 16 * w + (lane & 15);
            unsigned qoff = (unsigned)(qrow * ATT_STR + kk * 16 + (lane >> 4) * 8) * 2u;
            ldsm4(aq[0], aq[1], aq[2], aq[3], sQ + qoff);
#pragma unroll
            for (int nh = 0; nh < 4; nh++) {
                int krow = nh * 16 + (lane & 15);
                unsigned koff = (unsigned)(krow * ATT_STR + kk * 16 + (lane >> 4) * 8) * 2u;
                unsigned r0, r1, r2, r3;
                ldsm4(r0, r1, r2, r3, sK + koff);
                unsigned b0[2] = {r0, r2}, b1[2] = {r1, r3};
                mma16816(sc[2*nh],   aq, b0);
                mma16816(sc[2*nh+1], aq, b1);
            }
        }

        int q_a = q0 + qrow0, q_b = q_a + 8;
#pragma unroll
        for (int j = 0; j < 8; j++) {
#pragma unroll
            for (int r = 0; r < 4; r++) {
                int k = k0 + j * 8 + (lane & 3) * 2 + (r & 1);
                int q = (r < 2) ? q_a : q_b;
                int dlt = q - k; if (dlt < 0) dlt = -dlt;
                sc[j][r] = (dlt <= WIN_) ? sc[j][r] * 0.125f : -1e30f;
            }
        }
        float mx0 = -1e30f, mx1 = -1e30f;
#pragma unroll
        for (int j = 0; j < 8; j++) {
            mx0 = fmaxf(mx0, fmaxf(sc[j][0], sc[j][1]));
            mx1 = fmaxf(mx1, fmaxf(sc[j][2], sc[j][3]));
        }
        for (int off = 1; off < 4; off <<= 1) {
            mx0 = fmaxf(mx0, __shfl_xor_sync(0xffffffffu, mx0, off));
            mx1 = fmaxf(mx1, __shfl_xor_sync(0xffffffffu, mx1, off));
        }
        float mn0 = fmaxf(m0, mx0), mn1 = fmaxf(m1, mx1);
        float c0 = __expf(m0 - mn0), c1 = __expf(m1 - mn1);
        float rs0 = 0.f, rs1 = 0.f;
#pragma unroll
        for (int j = 0; j < 8; j++) {
            sc[j][0] = __expf(sc[j][0] - mn0);
            sc[j][1] = __expf(sc[j][1] - mn0);
            sc[j][2] = __expf(sc[j][2] - mn1);
            sc[j][3] = __expf(sc[j][3] - mn1);
            rs0 += sc[j][0] + sc[j][1];
            rs1 += sc[j][2] + sc[j][3];
        }
        for (int off = 1; off < 4; off <<= 1) {
            rs0 += __shfl_xor_sync(0xffffffffu, rs0, off);
            rs1 += __shfl_xor_sync(0xffffffffu, rs1, off);
        }
        l0s = l0s * c0 + rs0;
        l1s = l1s * c1 + rs1;
        m0 = mn0; m1 = mn1;
#pragma unroll
        for (int j = 0; j < 8; j++) {
            o[j][0] *= c0; o[j][1] *= c0;
            o[j][2] *= c1; o[j][3] *= c1;
        }

#pragma unroll
        for (int kc = 0; kc < 4; kc++) {
            unsigned ph[4];
            {
                __half2 p0 = __floats2half2_rn(sc[2*kc][0],   sc[2*kc][1]);
                __half2 p1 = __floats2half2_rn(sc[2*kc][2],   sc[2*kc][3]);
                __half2 p2 = __floats2half2_rn(sc[2*kc+1][0], sc[2*kc+1][1]);
                __half2 p3 = __floats2half2_rn(sc[2*kc+1][2], sc[2*kc+1][3]);
                ph[0] = *(unsigned*)&p0;
                ph[1] = *(unsigned*)&p1;
                ph[2] = *(unsigned*)&p2;
                ph[3] = *(unsigned*)&p3;
            }
#pragma unroll
            for (int nh = 0; nh < 4; nh++) {
                int vrow = kc * 16 + (lane & 15);
                unsigned voff = (unsigned)(vrow * ATT_STR + nh * 16 + (lane >> 4) * 8) * 2u;
                unsigned r0, r1, r2, r3;
                ldsm4t(r0, r1, r2, r3, sV + voff);
                unsigned b0[2] = {r0, r1}, b1[2] = {r2, r3};
                mma16816(o[2*nh],   ph, b0);
                mma16816(o[2*nh+1], ph, b1);
            }
        }
        __syncthreads();
    }

    float inv0 = 1.f / l0s, inv1 = 1.f / l1s;
    int qa = b * L_ + q0 + qrow0;
#pragma unroll
    for (int j = 0; j < 8; j++) {
        int c = h * DH_ + j * 8 + (lane & 3) * 2;
        *(__half2*)&g_ATTh[(size_t)qa * D_ + c] =
            __floats2half2_rn(o[j][0] * inv0, o[j][1] * inv0);
        *(__half2*)&g_ATTh[(size_t)(qa + 8) * D_ + c] =
            __floats2half2_rn(o[j][2] * inv1, o[j][3] * inv1);
    }
}

// ---------------- PDL launch helper ----------------
#define PDL_LAUNCH(kern, grid, block, smem, ...) do {                         \
    cudaLaunchConfig_t _cfg = {};                                             \
    _cfg.gridDim = (grid); _cfg.blockDim = (block);                           \
    _cfg.dynamicSmemBytes = (smem);                                           \
    cudaLaunchAttribute _at[1];                                               \
    _at[0].id = cudaLaunchAttributeProgrammaticStreamSerialization;           \
    _at[0].val.programmaticStreamSerializationAllowed = 1;                    \
    _cfg.attrs = _at; _cfg.numAttrs = 1;                                      \
    cudaLaunchKernelEx(&_cfg, kern, ##__VA_ARGS__);                           \
} while (0)

// ---------------- launcher ----------------
extern "C" void kernel_launch(void* const* d_in, const int* in_sizes, int n_in,
                              void* d_out, int out_size) {
    const float* context = (const float*)d_in[0];
    const float* conv_w  = (const float*)d_in[1];
    const float* Wx      = (const float*)d_in[2];
    const float* Wh      = (const float*)d_in[3];
    const float* Wout    = (const float*)d_in[4];
    const float* Aparam  = (const float*)d_in[5];
    const float* gm      = (const float*)d_in[6];
    const float* bm      = (const float*)d_in[7];
    const float* ga      = (const float*)d_in[8];
    const float* ba      = (const float*)d_in[9];
    const float* Wqkv    = (const float*)d_in[10];
    const float* bqkv    = (const float*)d_in[11];
    const float* Wo      = (const float*)d_in[12];
    const float* bo      = (const float*)d_in[13];
    float* out = (float*)d_out;

    static bool init = false;
    static void *pX, *pUh, *pXh, *pSEQh, *pQKVh, *pATTh, *pWxH, *pWqkvH, *pWoH;
    if (!init) {
        cudaGetSymbolAddress(&pX, g_X);
        cudaGetSymbolAddress(&pUh, g_Uh);
        cudaGetSymbolAddress(&pXh, g_Xh);
        cudaGetSymbolAddress(&pSEQh, g_SEQh);
        cudaGetSymbolAddress(&pQKVh, g_QKVh);
        cudaGetSymbolAddress(&pATTh, g_ATTh);
        cudaGetSymbolAddress(&pWxH, g_WxH);
        cudaGetSymbolAddress(&pWqkvH, g_WqkvH);
        cudaGetSymbolAddress(&pWoH, g_WoH);
        cudaFuncSetAttribute(attn_mma_kernel,
                             cudaFuncAttributeMaxDynamicSharedMemorySize,
                             5 * ATT_T * (int)sizeof(__half));
        cudaFuncSetAttribute(mma_gemm4<0>,
                             cudaFuncAttributeMaxDynamicSharedMemorySize,
                             (2 * GA_SZ + 2 * GB0_SZ) * (int)sizeof(__half));
        cudaFuncSetAttribute(mma_gemm4<1>,
                             cudaFuncAttributeMaxDynamicSharedMemorySize,
                             (2 * GA_SZ + 2 * GB1_SZ) * (int)sizeof(__half));
        cudaFuncSetAttribute(mma_gemm_conv,
                             cudaFuncAttributeMaxDynamicSharedMemorySize,
                             (2 * GA_SZ + 2 * GB0_SZ) * (int)sizeof(__half));
        init = true;
    }
    const size_t ATT_SMEM = 5 * ATT_T * sizeof(__half);
    const size_t G0_SMEM  = (2 * GA_SZ + 2 * GB0_SZ) * sizeof(__half);
    const size_t G1_SMEM  = (2 * GA_SZ + 2 * GB1_SZ) * sizeof(__half);

    PDL_LAUNCH(cvt_weights_all, dim3((NWX + NWQ + NWO + 255) / 256), dim3(256), 0,
               Wx, Wqkv, Wo);

    for (int i = 0; i < NL_; i++) {
        if (i == 0) {
            PDL_LAUNCH(conv_silu_f32, dim3(B_ * L_), dim3(128), 0, context, conv_w);
            PDL_LAUNCH(mma_gemm4<0>, dim3(S_ / 128, B_ * L_ / 128), dim3(256), G0_SMEM,
                       (const __half*)pXh, (const __half*)pWxH,
                       (const float*)nullptr, (float*)nullptr, (__half*)pUh,
                       B_ * L_, S_, D_);
        } else {
            PDL_LAUNCH(mma_gemm_conv, dim3(S_ / 128, B_ * L_ / 128), dim3(256), G0_SMEM,
                       (const __half*)pSEQh, conv_w + (size_t)i * 3 * D_,
                       (const __half*)pWxH + (size_t)i * D_ * S_,
                       (__half*)pUh, B_ * L_, S_, D_);
        }
        PDL_LAUNCH(ht_merged, dim3(B_, 128), dim3(256), 0,
                   Aparam + (size_t)i * S_, Wh + (size_t)i * D_ * S_,
                   Wout + (size_t)i * S_ * D_, i, i == 0 ? 1 : 0);
        const float* seqin = (i == 0) ? context : out;
        PDL_LAUNCH(ln_kernel, dim3(B_ * L_), dim3(128), 0,
                   seqin, (const float*)nullptr, gm, bm, out, 1, i < 5 ? 1 : 0);

        if (((i + 1) % 4) == 0) {
            PDL_LAUNCH(mma_gemm4<1>, dim3(3 * D_ / 128, B_ * L_ / 128), dim3(256), G1_SMEM,
                       (const __half*)pSEQh, (const __half*)pWqkvH,
                       bqkv, (float*)nullptr, (__half*)pQKVh, B_ * L_, 3 * D_, D_);
            PDL_LAUNCH(attn_mma_kernel, dim3(L_ / 64, H_, B_), dim3(128), ATT_SMEM);
            PDL_LAUNCH(mma_gemm4<1>, dim3(D_ / 128, B_ * L_ / 128), dim3(256), G1_SMEM,
                       (const __half*)pATTh, (const __half*)pWoH,
                       bo, (float*)pX, (__half*)nullptr, B_ * L_, D_, D_);
            PDL_LAUNCH(ln_kernel, dim3(B_ * L_), dim3(128), 0,
                       out, (const float*)pX, ga, ba, out, 0, 1);
        }
    }
}

// round 17
// speedup vs baseline: 1.3822x; 1.3822x over previous
#include <cuda_runtime.h>
#include <cuda_fp16.h>
#include <math.h>

#define B_   4
#define L_   2048
#define D_   512
#define S_   256
#define NL_  6
#define H_   8
#define DH_  64
#define WIN_ 256

// ---------------- scratch (device globals; no allocation) ----------------
__device__ float g_X[B_*L_*D_];         // out-proj fp32 scratch
__device__ float g_STATE[B_*D_];
__device__ float g_PART[128][B_][S_];

__device__ __half g_Uh[B_*L_*S_];       // mamba u (fp16)
__device__ __half g_Xh[B_*L_*D_];       // conv output (layer 0 only)
__device__ __half g_SEQh[B_*L_*D_];     // ln output fp16 shadow
__device__ __half g_QKVh[B_*L_*3*D_];   // qkv fp16
__device__ __half g_ATTh[B_*L_*D_];     // attention context fp16
__device__ __half g_WxH[NL_*D_*S_];     // [D][S]
__device__ __half g_WqkvH[3*D_*D_];     // [3D][D]
__device__ __half g_WoH[D_*D_];         // [D][D]

// ---------------- helpers ----------------
__device__ __forceinline__ void gds() {
    asm volatile("griddepcontrol.wait;" ::: "memory");
}
__device__ __forceinline__ void ldsm4(unsigned& r0, unsigned& r1, unsigned& r2, unsigned& r3, unsigned addr) {
    asm volatile("ldmatrix.sync.aligned.m8n8.x4.shared.b16 {%0,%1,%2,%3},[%4];"
                 : "=r"(r0), "=r"(r1), "=r"(r2), "=r"(r3) : "r"(addr));
}
__device__ __forceinline__ void ldsm4t(unsigned& r0, unsigned& r1, unsigned& r2, unsigned& r3, unsigned addr) {
    asm volatile("ldmatrix.sync.aligned.m8n8.x4.trans.shared.b16 {%0,%1,%2,%3},[%4];"
                 : "=r"(r0), "=r"(r1), "=r"(r2), "=r"(r3) : "r"(addr));
}
__device__ __forceinline__ void mma16816(float* c, const unsigned* a, const unsigned* b) {
    asm volatile("mma.sync.aligned.m16n8k16.row.col.f32.f16.f16.f32 "
                 "{%0,%1,%2,%3},{%4,%5,%6,%7},{%8,%9},{%0,%1,%2,%3};"
                 : "+f"(c[0]), "+f"(c[1]), "+f"(c[2]), "+f"(c[3])
                 : "r"(a[0]), "r"(a[1]), "r"(a[2]), "r"(a[3]), "r"(b[0]), "r"(b[1]));
}
__device__ __forceinline__ void cpa16(unsigned d, const void* s) {
    asm volatile("cp.async.cg.shared.global [%0],[%1],16;" :: "r"(d), "l"(s));
}
__device__ __forceinline__ void cpa_commit() {
    asm volatile("cp.async.commit_group;");
}
template <int N>
__device__ __forceinline__ void cpa_wait() {
    asm volatile("cp.async.wait_group %0;" :: "n"(N));
}

// ---------------- merged weight conversion ----------------
#define NWX (NL_*D_*S_)
#define NWQ (3*D_*D_)
#define NWO (D_*D_)
__global__ void cvt_weights_all(const float* __restrict__ Wx,
                                const float* __restrict__ Wqkv,
                                const float* __restrict__ Wo) {
    gds();
    int t = blockIdx.x * 256 + threadIdx.x;
    if (t < NWX) {
        g_WxH[t] = __float2half_rn(Wx[t]);
    } else if (t < NWX + NWQ) {
        int u = t - NWX;
        g_WqkvH[u] = __float2half_rn(Wqkv[u]);
    } else if (t < NWX + NWQ + NWO) {
        int u = t - NWX - NWQ;
        g_WoH[u] = __float2half_rn(Wo[u]);
    }
}

// ---------------- conv (k=3, causal) + SiLU -> fp16 (layer 0 only) ------
__global__ void conv_silu_f32(const float* __restrict__ seq,
                              const float* __restrict__ cw) {
    gds();
    int row = blockIdx.x;
    int l = row & (L_ - 1);
    int t = threadIdx.x;
    float4 z = make_float4(0.f, 0.f, 0.f, 0.f);
    float4 a0 = (l >= 2) ? ((const float4*)(seq + (size_t)(row - 2) * D_))[t] : z;
    float4 a1 = (l >= 1) ? ((const float4*)(seq + (size_t)(row - 1) * D_))[t] : z;
    float4 a2 = ((const float4*)(seq + (size_t)row * D_))[t];
    float4 w0 = ((const float4*)(cw        ))[t];
    float4 w1 = ((const float4*)(cw +   D_ ))[t];
    float4 w2 = ((const float4*)(cw + 2*D_ ))[t];
    float x0 = w0.x*a0.x + w1.x*a1.x + w2.x*a2.x;
    float x1 = w0.y*a0.y + w1.y*a1.y + w2.y*a2.y;
    float x2 = w0.z*a0.z + w1.z*a1.z + w2.z*a2.z;
    float x3 = w0.w*a0.w + w1.w*a1.w + w2.w*a2.w;
    x0 = x0 / (1.f + __expf(-x0));
    x1 = x1 / (1.f + __expf(-x1));
    x2 = x2 / (1.f + __expf(-x2));
    x3 = x3 / (1.f + __expf(-x3));
    size_t o = (size_t)row * D_ + t * 4;
    *(__half2*)&g_Xh[o]     = __floats2half2_rn(x0, x1);
    *(__half2*)&g_Xh[o + 2] = __floats2half2_rn(x2, x3);
}

// ---------------- fp16 cp.async GEMM, 128x128 tile, K-chunk 64 ----------
#define GA_STR 72
#define GA_SZ  (128 * GA_STR)
#define GB1_SZ (128 * GA_STR)
#define GB0_SZ (64 * 136)
extern __shared__ __half smg[];

template <int TB>
__global__ void __launch_bounds__(256) mma_gemm4(const __half* __restrict__ A,
                                                 const __half* __restrict__ Bm,
                                                 const float* __restrict__ bias,
                                                 float* __restrict__ Cf,
                                                 __half* __restrict__ Ch,
                                                 int M, int N, int K) {
    gds();
    constexpr int BSZ = TB ? GB1_SZ : GB0_SZ;
    int bm = blockIdx.y * 128, bn = blockIdx.x * 128;
    int tid = threadIdx.x;
    int lane = tid & 31, wid = tid >> 5;
    int wm = (wid & 3) * 32;
    int wn = (wid >> 2) * 64;

    float acc[2][8][4];
#pragma unroll
    for (int i = 0; i < 2; i++)
#pragma unroll
        for (int j = 0; j < 8; j++)
#pragma unroll
            for (int k = 0; k < 4; k++) acc[i][j][k] = 0.f;

    unsigned sbase = (unsigned)__cvta_generic_to_shared(smg);

    int nk = K >> 6;
    auto issue = [&](int kt) {
        unsigned sa = sbase + (unsigned)((kt & 1) * GA_SZ) * 2u;
        unsigned sb = sbase + (unsigned)(2 * GA_SZ + (kt & 1) * BSZ) * 2u;
        int k0 = kt << 6;
#pragma unroll
        for (int j = 0; j < 4; j++) {
            int ch = tid + 256 * j;
            int r = ch >> 3, c8 = (ch & 7) * 8;
            cpa16(sa + (unsigned)(r * GA_STR + c8) * 2u,
                  A + (size_t)(bm + r) * K + k0 + c8);
        }
        if (TB == 1) {
#pragma unroll
            for (int j = 0; j < 4; j++) {
                int ch = tid + 256 * j;
                int r = ch >> 3, c8 = (ch & 7) * 8;
                cpa16(sb + (unsigned)(r * GA_STR + c8) * 2u,
                      Bm + (size_t)(bn + r) * K + k0 + c8);
            }
        } else {
#pragma unroll
            for (int j = 0; j < 4; j++) {
                int ch = tid + 256 * j;
                int r = ch >> 4, c8 = (ch & 15) * 8;
                cpa16(sb + (unsigned)(r * 136 + c8) * 2u,
                      Bm + (size_t)(k0 + r) * N + bn + c8);
            }
        }
        cpa_commit();
    };

    issue(0);
    for (int kt = 0; kt < nk; kt++) {
        if (kt + 1 < nk) { issue(kt + 1); cpa_wait<1>(); }
        else             { cpa_wait<0>(); }
        __syncthreads();

        unsigned sa = sbase + (unsigned)((kt & 1) * GA_SZ) * 2u;
        unsigned sb = sbase + (unsigned)(2 * GA_SZ + (kt & 1) * BSZ) * 2u;
#pragma unroll
        for (int ks = 0; ks < 4; ks++) {
            unsigned af[2][4], bf[8][2];
#pragma unroll
            for (int mi = 0; mi < 2; mi++) {
                int row = wm + mi * 16 + (lane & 15);
                unsigned off = (unsigned)(row * GA_STR + ks * 16 + (lane >> 4) * 8) * 2u;
                ldsm4(af[mi][0], af[mi][1], af[mi][2], af[mi][3], sa + off);
            }
            if (TB == 1) {
#pragma unroll
                for (int nh = 0; nh < 4; nh++) {
                    int row = wn + nh * 16 + (lane & 15);
                    unsigned off = (unsigned)(row * GA_STR + ks * 16 + (lane >> 4) * 8) * 2u;
                    unsigned r0, r1, r2, r3;
                    ldsm4(r0, r1, r2, r3, sb + off);
                    bf[nh*2+0][0] = r0; bf[nh*2+0][1] = r2;
                    bf[nh*2+1][0] = r1; bf[nh*2+1][1] = r3;
                }
            } else {
#pragma unroll
                for (int nh = 0; nh < 4; nh++) {
                    int row = ks * 16 + (lane & 15);
                    unsigned off = (unsigned)(row * 136 + wn + nh * 16 + (lane >> 4) * 8) * 2u;
                    unsigned r0, r1, r2, r3;
                    ldsm4t(r0, r1, r2, r3, sb + off);
                    bf[nh*2+0][0] = r0; bf[nh*2+0][1] = r1;
                    bf[nh*2+1][0] = r2; bf[nh*2+1][1] = r3;
                }
            }
#pragma unroll
            for (int mi = 0; mi < 2; mi++)
#pragma unroll
                for (int ni = 0; ni < 8; ni++)
                    mma16816(acc[mi][ni], af[mi], bf[ni]);
        }
        __syncthreads();
    }

#pragma unroll
    for (int mi = 0; mi < 2; mi++)
#pragma unroll
        for (int ni = 0; ni < 8; ni++) {
            int r = bm + wm + mi * 16 + (lane >> 2);
            int c = bn + wn + ni * 8 + (lane & 3) * 2;
            float b0 = bias ? bias[c] : 0.f;
            float b1 = bias ? bias[c + 1] : 0.f;
            float v00 = acc[mi][ni][0] + b0, v01 = acc[mi][ni][1] + b1;
            float v10 = acc[mi][ni][2] + b0, v11 = acc[mi][ni][3] + b1;
            if (Ch) {
                *(__half2*)&Ch[(size_t)r * N + c]       = __floats2half2_rn(v00, v01);
                *(__half2*)&Ch[(size_t)(r + 8) * N + c] = __floats2half2_rn(v10, v11);
            } else {
                Cf[(size_t)r * N + c]           = v00;
                Cf[(size_t)r * N + c + 1]       = v01;
                Cf[(size_t)(r + 8) * N + c]     = v10;
                Cf[(size_t)(r + 8) * N + c + 1] = v11;
            }
        }
}

// ---------------- conv-fused mamba GEMM (layers 1-5) ----------------
__global__ void __launch_bounds__(256) mma_gemm_conv(const __half* __restrict__ SEQ,
                                                     const float* __restrict__ cw,
                                                     const __half* __restrict__ Bm,
                                                     __half* __restrict__ Ch,
                                                     int M, int N, int K) {
    gds();
    int bm = blockIdx.y * 128, bn = blockIdx.x * 128;
    int tid = threadIdx.x;
    int lane = tid & 31, wid = tid >> 5;
    int wm = (wid & 3) * 32;
    int wn = (wid >> 2) * 64;

    float acc[2][8][4];
#pragma unroll
    for (int i = 0; i < 2; i++)
#pragma unroll
        for (int j = 0; j < 8; j++)
#pragma unroll
            for (int k = 0; k < 4; k++) acc[i][j][k] = 0.f;

    unsigned sbase = (unsigned)__cvta_generic_to_shared(smg);
    int nk = K >> 6;

    uint4 v0[4], v1[4], v2[4];
    auto loadA = [&](int kt) {
        int k0 = kt << 6;
#pragma unroll
        for (int j = 0; j < 4; j++) {
            int ch = tid + 256 * j;
            int r = ch >> 3, c8 = (ch & 7) * 8;
            int row = bm + r;
            int l = row & (L_ - 1);
            size_t base = (size_t)row * K + k0 + c8;
            uint4 z4 = make_uint4(0u, 0u, 0u, 0u);
            v2[j] = *(const uint4*)(SEQ + base);
            v1[j] = (l >= 1) ? *(const uint4*)(SEQ + base - K) : z4;
            v0[j] = (l >= 2) ? *(const uint4*)(SEQ + base - 2 * K) : z4;
        }
    };
    auto storeA = [&](int kt) {
        int k0 = kt << 6;
#pragma unroll
        for (int j = 0; j < 4; j++) {
            int ch = tid + 256 * j;
            int r = ch >> 3, c8 = (ch & 7) * 8;
            const float* cp = cw + k0 + c8;
            float4 wa0 = *(const float4*)(cp);
            float4 wb0 = *(const float4*)(cp + 4);
            float4 wa1 = *(const float4*)(cp + D_);
            float4 wb1 = *(const float4*)(cp + D_ + 4);
            float4 wa2 = *(const float4*)(cp + 2 * D_);
            float4 wb2 = *(const float4*)(cp + 2 * D_ + 4);
            float w0[8] = {wa0.x, wa0.y, wa0.z, wa0.w, wb0.x, wb0.y, wb0.z, wb0.w};
            float w1[8] = {wa1.x, wa1.y, wa1.z, wa1.w, wb1.x, wb1.y, wb1.z, wb1.w};
            float w2[8] = {wa2.x, wa2.y, wa2.z, wa2.w, wb2.x, wb2.y, wb2.z, wb2.w};
            const __half2* h0 = (const __half2*)&v0[j];
            const __half2* h1 = (const __half2*)&v1[j];
            const __half2* h2 = (const __half2*)&v2[j];
            uint4 outv;
            __half2* ov = (__half2*)&outv;
#pragma unroll
            for (int e = 0; e < 4; e++) {
                float2 f0 = __half22float2(h0[e]);
                float2 f1 = __half22float2(h1[e]);
                float2 f2 = __half22float2(h2[e]);
                float xa = w0[2*e]   * f0.x + w1[2*e]   * f1.x + w2[2*e]   * f2.x;
                float xb = w0[2*e+1] * f0.y + w1[2*e+1] * f1.y + w2[2*e+1] * f2.y;
                xa = xa / (1.f + __expf(-xa));
                xb = xb / (1.f + __expf(-xb));
                ov[e] = __floats2half2_rn(xa, xb);
            }
            *(uint4*)((char*)smg + (size_t)((kt & 1) * GA_SZ + r * GA_STR + c8) * 2) = outv;
        }
    };
    auto issueB = [&](int kt) {
        unsigned sb = sbase + (unsigned)(2 * GA_SZ + (kt & 1) * GB0_SZ) * 2u;
        int k0 = kt << 6;
#pragma unroll
        for (int j = 0; j < 4; j++) {
            int ch = tid + 256 * j;
            int r = ch >> 4, c8 = (ch & 15) * 8;
            cpa16(sb + (unsigned)(r * 136 + c8) * 2u,
                  Bm + (size_t)(k0 + r) * N + bn + c8);
        }
        cpa_commit();
    };

    loadA(0);
    issueB(0);
    for (int kt = 0; kt < nk; kt++) {
        storeA(kt);
        if (kt + 1 < nk) { issueB(kt + 1); loadA(kt + 1); cpa_wait<1>(); }
        else             { cpa_wait<0>(); }
        __syncthreads();

        unsigned sa = sbase + (unsigned)((kt & 1) * GA_SZ) * 2u;
        unsigned sb = sbase + (unsigned)(2 * GA_SZ + (kt & 1) * GB0_SZ) * 2u;
#pragma unroll
        for (int ks = 0; ks < 4; ks++) {
            unsigned af[2][4], bf[8][2];
#pragma unroll
            for (int mi = 0; mi < 2; mi++) {
                int row = wm + mi * 16 + (lane & 15);
                unsigned off = (unsigned)(row * GA_STR + ks * 16 + (lane >> 4) * 8) * 2u;
                ldsm4(af[mi][0], af[mi][1], af[mi][2], af[mi][3], sa + off);
            }
#pragma unroll
            for (int nh = 0; nh < 4; nh++) {
                int row = ks * 16 + (lane & 15);
                unsigned off = (unsigned)(row * 136 + wn + nh * 16 + (lane >> 4) * 8) * 2u;
                unsigned r0, r1, r2, r3;
                ldsm4t(r0, r1, r2, r3, sb + off);
                bf[nh*2+0][0] = r0; bf[nh*2+0][1] = r1;
                bf[nh*2+1][0] = r2; bf[nh*2+1][1] = r3;
            }
#pragma unroll
            for (int mi = 0; mi < 2; mi++)
#pragma unroll
                for (int ni = 0; ni < 8; ni++)
                    mma16816(acc[mi][ni], af[mi], bf[ni]);
        }
        __syncthreads();
    }

#pragma unroll
    for (int mi = 0; mi < 2; mi++)
#pragma unroll
        for (int ni = 0; ni < 8; ni++) {
            int r = bm + wm + mi * 16 + (lane >> 2);
            int c = bn + wn + ni * 8 + (lane & 3) * 2;
            *(__half2*)&Ch[(size_t)r * N + c] =
                __floats2half2_rn(acc[mi][ni][0], acc[mi][ni][1]);
            *(__half2*)&Ch[(size_t)(r + 8) * N + c] =
                __floats2half2_rn(acc[mi][ni][2], acc[mi][ni][3]);
        }
}

// ---------------- ssm chunked Horner (chunks of 16, fp16 U) -------------
__global__ void ht_part_kernel(const float* __restrict__ Aparam) {
    gds();
    int b = blockIdx.x, c = blockIdx.y;   // 128 chunks of 16
    int s = threadIdx.x;                  // 256
    float a = 1.f / (1.f + expf(-Aparam[s]));
    float wt = powf(a, (float)(16 * (127 - c)));
    float wmax = wt;
    for (int off = 16; off; off >>= 1)
        wmax = fmaxf(wmax, __shfl_xor_sync(0xffffffffu, wmax, off));
    if (wmax < 1e-28f) { g_PART[c][b][s] = 0.f; return; }
    const __half* base = g_Uh + ((size_t)(b * L_) + c * 16) * S_ + s;
    float p = 0.f;
#pragma unroll
    for (int j = 0; j < 16; j++) p = p * a + __half2float(base[(size_t)j * S_]);
    g_PART[c][b][s] = p * wt;
}

// ---------------- fused ht_combine + stateout (split-half phase 1) -------
__global__ void __launch_bounds__(512) ht_fused_kernel(const float* __restrict__ Aparam,
                                                       const float* __restrict__ Wh,
                                                       const float* __restrict__ Wout,
                                                       int first) {
    gds();
    __shared__ float sh_h0[2][S_];
    __shared__ float sh_ps[2][S_];
    __shared__ float sh_ht[S_];
    int b = blockIdx.x;
    int tid = threadIdx.x;
    int s = tid & 255, half = tid >> 8;
    {
        float h0 = 0.f;
        if (!first) {
            int d0 = half * 256;
#pragma unroll 8
            for (int d = d0; d < d0 + 256; d++)
                h0 += g_STATE[b * D_ + d] * Wh[(size_t)d * S_ + s];
        }
        float ps = 0.f;
        int c0 = half * 64;
#pragma unroll
        for (int c = 0; c < 64; c++) ps += g_PART[c0 + c][b][s];
        sh_h0[half][s] = h0;
        sh_ps[half][s] = ps;
    }
    __syncthreads();
    if (tid < S_) {
        float a = 1.f / (1.f + expf(-Aparam[s]));
        sh_ht[s] = powf(a, (float)L_) * (sh_h0[0][s] + sh_h0[1][s])
                 + sh_ps[0][s] + sh_ps[1][s];
    }
    __syncthreads();
    int d = tid;
    float acc = 0.f;
#pragma unroll 8
    for (int ss = 0; ss < S_; ss++) acc += sh_ht[ss] * Wout[(size_t)ss * D_ + d];
    g_STATE[b * D_ + d] = acc;
}

// ---------------- residual + LayerNorm (optional fp16 shadow) ------------
__global__ void ln_kernel(const float* __restrict__ seq, const float* __restrict__ add,
                          const float* __restrict__ gamma, const float* __restrict__ beta,
                          float* __restrict__ out, int bcast, int writeh) {
    gds();
    __shared__ float red[4];
    __shared__ float stat;
    int row = blockIdx.x;
    int b = row >> 11;
    int t = threadIdx.x;   // 128
    float4 x = ((const float4*)(seq + (size_t)row * D_))[t];
    const float* ap = bcast ? (g_STATE + (size_t)b * D_) : (add + (size_t)row * D_);
    float4 a4 = ((const float4*)ap)[t];
    x.x += a4.x; x.y += a4.y; x.z += a4.z; x.w += a4.w;

    float sum = x.x + x.y + x.z + x.w;
    for (int off = 16; off; off >>= 1) sum += __shfl_xor_sync(0xffffffffu, sum, off);
    if ((t & 31) == 0) red[t >> 5] = sum;
    __syncthreads();
    if (t == 0) stat = (red[0] + red[1] + red[2] + red[3]) * (1.f / D_);
    __syncthreads();
    float mu = stat;
    float d0 = x.x - mu, d1 = x.y - mu, d2 = x.z - mu, d3 = x.w - mu;
    float sq = d0*d0 + d1*d1 + d2*d2 + d3*d3;
    for (int off = 16; off; off >>= 1) sq += __shfl_xor_sync(0xffffffffu, sq, off);
    if ((t & 31) == 0) red[t >> 5] = sq;
    __syncthreads();
    if (t == 0) stat = rsqrtf((red[0] + red[1] + red[2] + red[3]) * (1.f / D_) + 1e-5f);
    __syncthreads();
    float rs = stat;
    float4 g = ((const float4*)gamma)[t], be = ((const float4*)beta)[t];
    float4 y;
    y.x = d0 * rs * g.x + be.x;
    y.y = d1 * rs * g.y + be.y;
    y.z = d2 * rs * g.z + be.z;
    y.w = d3 * rs * g.w + be.w;
    ((float4*)(out + (size_t)row * D_))[t] = y;
    if (writeh) {
        size_t o = (size_t)row * D_ + t * 4;
        *(__half2*)&g_SEQh[o]     = __floats2half2_rn(y.x, y.y);
        *(__half2*)&g_SEQh[o + 2] = __floats2half2_rn(y.z, y.w);
    }
}

// ---------------- banded flash attention, fp16 MMA, cp.async K/V pipe ---
#define ATT_STR 72
#define ATT_T   (64 * ATT_STR)
extern __shared__ __half s_att[];

__global__ void __launch_bounds__(128) attn_mma_kernel() {
    gds();
    int b = blockIdx.z, h = blockIdx.y, q0 = blockIdx.x * 64;
    int tid = threadIdx.x, lane = tid & 31, w = tid >> 5;

    unsigned sQ = (unsigned)__cvta_generic_to_shared(s_att);

    int kstart = q0 - WIN_; if (kstart < 0) kstart = 0;
    int kend = q0 + 64 + WIN_; if (kend > L_) kend = L_;
    int nkt = (kend - kstart) >> 6;

    auto issue = [&](int t) {
        unsigned sk = sQ + (unsigned)(ATT_T * (1 + 2 * (t & 1))) * 2u;
        unsigned sv = sk + (unsigned)ATT_T * 2u;
        int k0 = kstart + t * 64;
#pragma unroll
        for (int j = 0; j < 4; j++) {
            int idx = tid + 128 * j;
            int r = idx >> 3, c = (idx & 7) * 8;
            size_t base = (size_t)(b * L_ + k0 + r) * (3 * D_) + h * DH_ + c;
            unsigned doff = (unsigned)(r * ATT_STR + c) * 2u;
            cpa16(sk + doff, g_QKVh + base + D_);
            cpa16(sv + doff, g_QKVh + base + 2 * D_);
        }
        cpa_commit();
    };

    issue(0);
#pragma unroll
    for (int j = 0; j < 4; j++) {
        int idx = tid + 128 * j;
        int r = idx >> 3, c = (idx & 7) * 8;
        *(uint4*)&s_att[r * ATT_STR + c] =
            *(const uint4*)(g_QKVh + (size_t)(b * L_ + q0 + r) * (3 * D_) + h * DH_ + c);
    }

    float m0 = -1e30f, m1 = -1e30f, l0s = 0.f, l1s = 0.f;
    float o[8][4];
#pragma unroll
    for (int j = 0; j < 8; j++)
#pragma unroll
        for (int r = 0; r < 4; r++) o[j][r] = 0.f;

    int qrow0 = 16 * w + (lane >> 2);

    for (int t = 0; t < nkt; t++) {
        if (t + 1 < nkt) { issue(t + 1); cpa_wait<1>(); }
        else             { cpa_wait<0>(); }
        __syncthreads();

        unsigned sK = sQ + (unsigned)(ATT_T * (1 + 2 * (t & 1))) * 2u;
        unsigned sV = sK + (unsigned)ATT_T * 2u;
        int k0 = kstart + t * 64;

        float sc[8][4];
#pragma unroll
        for (int j = 0; j < 8; j++)
#pragma unroll
            for (int r = 0; r < 4; r++) sc[j][r] = 0.f;

#pragma unroll
        for (int kk = 0; kk < 4; kk++) {
            unsigned aq[4];
            int qrow = 16 * w + (lane & 15);
            unsigned qoff = (unsigned)(qrow * ATT_STR + kk * 16 + (lane >> 4) * 8) * 2u;
            ldsm4(aq[0], aq[1], aq[2], aq[3], sQ + qoff);
#pragma unroll
            for (int nh = 0; nh < 4; nh++) {
                int krow = nh * 16 + (lane & 15);
                unsigned koff = (unsigned)(krow * ATT_STR + kk * 16 + (lane >> 4) * 8) * 2u;
                unsigned r0, r1, r2, r3;
                ldsm4(r0, r1, r2, r3, sK + koff);
                unsigned b0[2] = {r0, r2}, b1[2] = {r1, r3};
                mma16816(sc[2*nh],   aq, b0);
                mma16816(sc[2*nh+1], aq, b1);
            }
        }

        int q_a = q0 + qrow0, q_b = q_a + 8;
#pragma unroll
        for (int j = 0; j < 8; j++) {
#pragma unroll
            for (int r = 0; r < 4; r++) {
                int k = k0 + j * 8 + (lane & 3) * 2 + (r & 1);
                int q = (r < 2) ? q_a : q_b;
                int dlt = q - k; if (dlt < 0) dlt = -dlt;
                sc[j][r] = (dlt <= WIN_) ? sc[j][r] * 0.125f : -1e30f;
            }
        }
        float mx0 = -1e30f, mx1 = -1e30f;
#pragma unroll
        for (int j = 0; j < 8; j++) {
            mx0 = fmaxf(mx0, fmaxf(sc[j][0], sc[j][1]));
            mx1 = fmaxf(mx1, fmaxf(sc[j][2], sc[j][3]));
        }
        for (int off = 1; off < 4; off <<= 1) {
            mx0 = fmaxf(mx0, __shfl_xor_sync(0xffffffffu, mx0, off));
            mx1 = fmaxf(mx1, __shfl_xor_sync(0xffffffffu, mx1, off));
        }
        float mn0 = fmaxf(m0, mx0), mn1 = fmaxf(m1, mx1);
        float c0 = __expf(m0 - mn0), c1 = __expf(m1 - mn1);
        float rs0 = 0.f, rs1 = 0.f;
#pragma unroll
        for (int j = 0; j < 8; j++) {
            sc[j][0] = __expf(sc[j][0] - mn0);
            sc[j][1] = __expf(sc[j][1] - mn0);
            sc[j][2] = __expf(sc[j][2] - mn1);
            sc[j][3] = __expf(sc[j][3] - mn1);
            rs0 += sc[j][0] + sc[j][1];
            rs1 += sc[j][2] + sc[j][3];
        }
        for (int off = 1; off < 4; off <<= 1) {
            rs0 += __shfl_xor_sync(0xffffffffu, rs0, off);
            rs1 += __shfl_xor_sync(0xffffffffu, rs1, off);
        }
        l0s = l0s * c0 + rs0;
        l1s = l1s * c1 + rs1;
        m0 = mn0; m1 = mn1;
#pragma unroll
        for (int j = 0; j < 8; j++) {
            o[j][0] *= c0; o[j][1] *= c0;
            o[j][2] *= c1; o[j][3] *= c1;
        }

#pragma unroll
        for (int kc = 0; kc < 4; kc++) {
            unsigned ph[4];
            {
                __half2 p0 = __floats2half2_rn(sc[2*kc][0],   sc[2*kc][1]);
                __half2 p1 = __floats2half2_rn(sc[2*kc][2],   sc[2*kc][3]);
                __half2 p2 = __floats2half2_rn(sc[2*kc+1][0], sc[2*kc+1][1]);
                __half2 p3 = __floats2half2_rn(sc[2*kc+1][2], sc[2*kc+1][3]);
                ph[0] = *(unsigned*)&p0;
                ph[1] = *(unsigned*)&p1;
                ph[2] = *(unsigned*)&p2;
                ph[3] = *(unsigned*)&p3;
            }
#pragma unroll
            for (int nh = 0; nh < 4; nh++) {
                int vrow = kc * 16 + (lane & 15);
                unsigned voff = (unsigned)(vrow * ATT_STR + nh * 16 + (lane >> 4) * 8) * 2u;
                unsigned r0, r1, r2, r3;
                ldsm4t(r0, r1, r2, r3, sV + voff);
                unsigned b0[2] = {r0, r1}, b1[2] = {r2, r3};
                mma16816(o[2*nh],   ph, b0);
                mma16816(o[2*nh+1], ph, b1);
            }
        }
        __syncthreads();
    }

    float inv0 = 1.f / l0s, inv1 = 1.f / l1s;
    int qa = b * L_ + q0 + qrow0;
#pragma unroll
    for (int j = 0; j < 8; j++) {
        int c = h * DH_ + j * 8 + (lane & 3) * 2;
        *(__half2*)&g_ATTh[(size_t)qa * D_ + c] =
            __floats2half2_rn(o[j][0] * inv0, o[j][1] * inv0);
        *(__half2*)&g_ATTh[(size_t)(qa + 8) * D_ + c] =
            __floats2half2_rn(o[j][2] * inv1, o[j][3] * inv1);
    }
}

// ---------------- PDL launch helper ----------------
#define PDL_LAUNCH(kern, grid, block, smem, ...) do {                         \
    cudaLaunchConfig_t _cfg = {};                                             \
    _cfg.gridDim = (grid); _cfg.blockDim = (block);                           \
    _cfg.dynamicSmemBytes = (smem);                                           \
    cudaLaunchAttribute _at[1];                                               \
    _at[0].id = cudaLaunchAttributeProgrammaticStreamSerialization;           \
    _at[0].val.programmaticStreamSerializationAllowed = 1;                    \
    _cfg.attrs = _at; _cfg.numAttrs = 1;                                      \
    cudaLaunchKernelEx(&_cfg, kern, ##__VA_ARGS__);                           \
} while (0)

// ---------------- launcher ----------------
extern "C" void kernel_launch(void* const* d_in, const int* in_sizes, int n_in,
                              void* d_out, int out_size) {
    const float* context = (const float*)d_in[0];
    const float* conv_w  = (const float*)d_in[1];
    const float* Wx      = (const float*)d_in[2];
    const float* Wh      = (const float*)d_in[3];
    const float* Wout    = (const float*)d_in[4];
    const float* Aparam  = (const float*)d_in[5];
    const float* gm      = (const float*)d_in[6];
    const float* bm      = (const float*)d_in[7];
    const float* ga      = (const float*)d_in[8];
    const float* ba      = (const float*)d_in[9];
    const float* Wqkv    = (const float*)d_in[10];
    const float* bqkv    = (const float*)d_in[11];
    const float* Wo      = (const float*)d_in[12];
    const float* bo      = (const float*)d_in[13];
    float* out = (float*)d_out;

    static bool init = false;
    static void *pX, *pUh, *pXh, *pSEQh, *pQKVh, *pATTh, *pWxH, *pWqkvH, *pWoH;
    if (!init) {
        cudaGetSymbolAddress(&pX, g_X);
        cudaGetSymbolAddress(&pUh, g_Uh);
        cudaGetSymbolAddress(&pXh, g_Xh);
        cudaGetSymbolAddress(&pSEQh, g_SEQh);
        cudaGetSymbolAddress(&pQKVh, g_QKVh);
        cudaGetSymbolAddress(&pATTh, g_ATTh);
        cudaGetSymbolAddress(&pWxH, g_WxH);
        cudaGetSymbolAddress(&pWqkvH, g_WqkvH);
        cudaGetSymbolAddress(&pWoH, g_WoH);
        cudaFuncSetAttribute(attn_mma_kernel,
                             cudaFuncAttributeMaxDynamicSharedMemorySize,
                             5 * ATT_T * (int)sizeof(__half));
        cudaFuncSetAttribute(mma_gemm4<0>,
                             cudaFuncAttributeMaxDynamicSharedMemorySize,
                             (2 * GA_SZ + 2 * GB0_SZ) * (int)sizeof(__half));
        cudaFuncSetAttribute(mma_gemm4<1>,
                             cudaFuncAttributeMaxDynamicSharedMemorySize,
                             (2 * GA_SZ + 2 * GB1_SZ) * (int)sizeof(__half));
        cudaFuncSetAttribute(mma_gemm_conv,
                             cudaFuncAttributeMaxDynamicSharedMemorySize,
                             (2 * GA_SZ + 2 * GB0_SZ) * (int)sizeof(__half));
        init = true;
    }
    const size_t ATT_SMEM = 5 * ATT_T * sizeof(__half);
    const size_t G0_SMEM  = (2 * GA_SZ + 2 * GB0_SZ) * sizeof(__half);
    const size_t G1_SMEM  = (2 * GA_SZ + 2 * GB1_SZ) * sizeof(__half);

    PDL_LAUNCH(cvt_weights_all, dim3((NWX + NWQ + NWO + 255) / 256), dim3(256), 0,
               Wx, Wqkv, Wo);

    for (int i = 0; i < NL_; i++) {
        if (i == 0) {
            PDL_LAUNCH(conv_silu_f32, dim3(B_ * L_), dim3(128), 0, context, conv_w);
            PDL_LAUNCH(mma_gemm4<0>, dim3(S_ / 128, B_ * L_ / 128), dim3(256), G0_SMEM,
                       (const __half*)pXh, (const __half*)pWxH,
                       (const float*)nullptr, (float*)nullptr, (__half*)pUh,
                       B_ * L_, S_, D_);
        } else {
            PDL_LAUNCH(mma_gemm_conv, dim3(S_ / 128, B_ * L_ / 128), dim3(256), G0_SMEM,
                       (const __half*)pSEQh, conv_w + (size_t)i * 3 * D_,
                       (const __half*)pWxH + (size_t)i * D_ * S_,
                       (__half*)pUh, B_ * L_, S_, D_);
        }
        PDL_LAUNCH(ht_part_kernel, dim3(B_, 128), dim3(256), 0,
                   Aparam + (size_t)i * S_);
        PDL_LAUNCH(ht_fused_kernel, dim3(B_), dim3(512), 0,
                   Aparam + (size_t)i * S_, Wh + (size_t)i * D_ * S_,
                   Wout + (size_t)i * S_ * D_, i == 0 ? 1 : 0);
        const float* seqin = (i == 0) ? context : out;
        PDL_LAUNCH(ln_kernel, dim3(B_ * L_), dim3(128), 0,
                   seqin, (const float*)nullptr, gm, bm, out, 1, i < 5 ? 1 : 0);

        if (((i + 1) % 4) == 0) {
            PDL_LAUNCH(mma_gemm4<1>, dim3(3 * D_ / 128, B_ * L_ / 128), dim3(256), G1_SMEM,
                       (const __half*)pSEQh, (const __half*)pWqkvH,
                       bqkv, (float*)nullptr, (__half*)pQKVh, B_ * L_, 3 * D_, D_);
            PDL_LAUNCH(attn_mma_kernel, dim3(L_ / 64, H_, B_), dim3(128), ATT_SMEM);
            PDL_LAUNCH(mma_gemm4<1>, dim3(D_ / 128, B_ * L_ / 128), dim3(256), G1_SMEM,
                       (const __half*)pATTh, (const __half*)pWoH,
                       bo, (float*)pX, (__half*)nullptr, B_ * L_, D_, D_);
            PDL_LAUNCH(ln_kernel, dim3(B_ * L_), dim3(128), 0,
                       out, (const float*)pX, ga, ba, out, 0, 1);
        }
    }
}